// round 6
// baseline (speedup 1.0000x reference)
#include <cuda_runtime.h>
#include <cstdint>

// HaarWaveletTopK on GB300 (sm_103a)
// k1: pass1  — Haar transform (main) + per-chunk top-8 candidates (float2 lanes)
// k2: zero×3 — detail zero-fill, float4 grid-stride memset in 3 slices
// k3: pass2  — warp-per-column candidate merge + sparse scatter into detail
// x: (B=8, T=8192, F=512) fp32.  out = [main | detail], each (B,T,F).

#define DIM_B 8
#define DIM_T 8192
#define DIM_T2 4096
#define DIM_F 512
#define DIM_F2 (DIM_F / 2)             // 256 float2 per row

#define TOPK 8
#define NC 16                           // t-chunks per column
#define T_PER_CHUNK (DIM_T2 / NC)       // 256
#define TSEG 8                          // warps per block
#define NTHREADS (32 * TSEG)            // 256
#define T_PER_THREAD (T_PER_CHUNK / TSEG)   // 32
#define FBLK 64                         // f-columns per block (2 per lane)
#define NCAND (NC * TOPK)               // 128 candidates per column

typedef unsigned long long u64;
typedef unsigned int u32;

// Packed candidates: [col][q], col = b*512+f, q = chunk*8+j.  4 MB.
__device__ u64 g_cand[DIM_B * DIM_F * NCAND];

__device__ __forceinline__ u64 pack_cand(float k, int p)
{
    return ((u64)__float_as_uint(k) << 32) | (u32)p;   // k >= 0 -> monotone
}

__device__ __forceinline__ void topk_insert(float (&key)[TOPK], int (&pay)[TOPK],
                                            float a, int p)
{
    if (a > key[TOPK - 1]) {
        key[TOPK - 1] = a;
        pay[TOPK - 1] = p;
#pragma unroll
        for (int j = TOPK - 1; j > 0; --j) {
            if (key[j] > key[j - 1]) {
                float tk = key[j]; key[j] = key[j - 1]; key[j - 1] = tk;
                int   tp = pay[j]; pay[j] = pay[j - 1]; pay[j - 1] = tp;
            }
        }
    }
}

// ---------------------------------------------------------------------------
// Pass 1: main transform + per-chunk top-8. NO detail writes (separate memset).
// ---------------------------------------------------------------------------
__global__ __launch_bounds__(NTHREADS)
void haar_pass1(const float2* __restrict__ x2,
                float2* __restrict__ m2)
{
    __shared__ u64 s_cand[FBLK][TSEG * TOPK + 1];

    const int lane = threadIdx.x & 31;
    const int ts   = threadIdx.x >> 5;        // warp id = t-segment
    const int b    = blockIdx.y;
    const int c    = blockIdx.z;
    const int fc   = blockIdx.x * 32 + lane;  // float2 column index (0..255)

    const float2* __restrict__ xb = x2 + (size_t)b * DIM_T * DIM_F2;
    float2* __restrict__ mb       = m2 + (size_t)b * DIM_T * DIM_F2;

    float k0[TOPK], k1[TOPK];
    int   p0[TOPK], p1[TOPK];
#pragma unroll
    for (int j = 0; j < TOPK; ++j) { k0[j] = 0.0f; p0[j] = 0; k1[j] = 0.0f; p1[j] = 0; }

    const int t0 = c * T_PER_CHUNK + ts * T_PER_THREAD;

#pragma unroll 4
    for (int i = 0; i < T_PER_THREAD; ++i) {
        const int t = t0 + i;
        const size_t re = (size_t)(2 * t) * DIM_F2 + fc;   // even row, float2 units
        const float2 e = xb[re];
        const float2 o = xb[re + DIM_F2];

        float2 low;
        low.x = (e.x + o.x) * 0.5f;
        low.y = (e.y + o.y) * 0.5f;
        const float hx = e.x - o.x;
        const float hy = e.y - o.y;

        mb[re]          = low;
        mb[re + DIM_F2] = low;

        topk_insert(k0, p0, fabsf(hx), (t << 1) | (hx < 0.0f ? 1 : 0));
        topk_insert(k1, p1, fabsf(hy), (t << 1) | (hy < 0.0f ? 1 : 0));
    }

    // Publish per-thread candidates for both owned columns
#pragma unroll
    for (int j = 0; j < TOPK; ++j) {
        s_cand[2 * lane][ts * TOPK + j]     = pack_cand(k0[j], p0[j]);
        s_cand[2 * lane + 1][ts * TOPK + j] = pack_cand(k1[j], p1[j]);
    }
    __syncthreads();

    // Warp 0: each lane merges its 2 columns (64 candidates each), spills top-8.
    if (ts == 0) {
#pragma unroll
        for (int half = 0; half < 2; ++half) {
            const int col_l = 2 * lane + half;
            u64 best[TOPK];
#pragma unroll
            for (int j = 0; j < TOPK; ++j) best[j] = 0;

#pragma unroll 4
            for (int q = 0; q < TSEG * TOPK; ++q) {
                const u64 v = s_cand[col_l][q];
                if (v > best[TOPK - 1]) {
                    best[TOPK - 1] = v;
#pragma unroll
                    for (int j = TOPK - 1; j > 0; --j) {
                        if (best[j] > best[j - 1]) {
                            u64 tv = best[j]; best[j] = best[j - 1]; best[j - 1] = tv;
                        }
                    }
                }
            }

            const int f = blockIdx.x * FBLK + col_l;
            const size_t base = ((size_t)(b * DIM_F + f)) * NCAND + (size_t)c * TOPK;
#pragma unroll
            for (int j = 0; j < TOPK; ++j)
                g_cand[base + j] = best[j];
        }
    }
}

// ---------------------------------------------------------------------------
// Detail zero-fill: pure float4 streaming memset over a slice.
// ---------------------------------------------------------------------------
__global__ __launch_bounds__(256)
void det_zero(float4* __restrict__ p, long long n4)
{
    const float4 z = make_float4(0.f, 0.f, 0.f, 0.f);
    long long i = (long long)blockIdx.x * blockDim.x + threadIdx.x;
    const long long stride = (long long)gridDim.x * blockDim.x;
    for (; i < n4; i += stride)
        p[i] = z;
}

// ---------------------------------------------------------------------------
// Pass 2: one warp per (b,f) column — merge 128 candidates, scatter 16 values.
// ---------------------------------------------------------------------------
__global__ __launch_bounds__(256)
void haar_pass2(float* __restrict__ out_det)
{
    const int wid_in_blk = threadIdx.x >> 5;
    const int lane       = threadIdx.x & 31;
    const int col        = blockIdx.x * 8 + wid_in_blk;   // 0..4095
    const int b          = col >> 9;
    const int f          = col & (DIM_F - 1);

    const size_t base = (size_t)col * NCAND;

    u64 v0 = g_cand[base + lane];
    u64 v1 = g_cand[base + lane + 32];
    u64 v2 = g_cand[base + lane + 64];
    u64 v3 = g_cand[base + lane + 96];

    // Sort 4 descending (network)
    u64 t;
    if (v0 < v1) { t = v0; v0 = v1; v1 = t; }
    if (v2 < v3) { t = v2; v2 = v3; v3 = t; }
    if (v0 < v2) { t = v0; v0 = v2; v2 = t; }
    if (v1 < v3) { t = v1; v1 = v3; v3 = t; }
    if (v1 < v2) { t = v1; v1 = v2; v2 = t; }

    u64 res = 0;   // lane r holds round-r winner
#pragma unroll
    for (int r = 0; r < TOPK; ++r) {
        u64 head = v0;
#pragma unroll
        for (int off = 16; off > 0; off >>= 1) {
            const u64 other = __shfl_xor_sync(0xFFFFFFFFu, head, off);
            if (other > head) head = other;
        }
        const bool mine = (v0 == head) && (head != 0);
        const unsigned m = __ballot_sync(0xFFFFFFFFu, mine);
        const int winner = __ffs(m) - 1;
        if (lane == winner) { v0 = v1; v1 = v2; v2 = v3; v3 = 0; }
        if (lane == r) res = head;
    }

    if (lane < TOPK) {
        const u32 payv = (u32)res;
        const float k  = __uint_as_float((u32)(res >> 32));
        float val      = k * 0.5f;                 // |e-o|*0.5 = |high_half|
        if (payv & 1) val = -val;
        const int tt   = payv >> 1;
        float* __restrict__ db = out_det + (size_t)b * DIM_T * DIM_F;
        const size_t r0 = (size_t)(2 * tt) * DIM_F + f;
        db[r0]         = val;
        db[r0 + DIM_F] = -val;
    }
}

extern "C" void kernel_launch(void* const* d_in, const int* in_sizes, int n_in,
                              void* d_out, int out_size)
{
    const float* x = (const float*)d_in[0];
    float* out = (float*)d_out;
    const size_t N = (size_t)out_size / 2;    // elements in `main`
    float* det = out + N;

    // 1) pass1 (main + candidates)
    dim3 grid1(DIM_F2 / 32, DIM_B, NC);       // 8 x 8 x 16 = 1024 blocks
    haar_pass1<<<grid1, NTHREADS>>>((const float2*)x, (float2*)out);

    // 2) detail zero-fill, 3 slices (also positions ncu capture on pass1)
    const long long n4 = (long long)N / 4;
    const long long S  = (n4 + 2) / 3;
    for (int s = 0; s < 3; ++s) {
        const long long off = (long long)s * S;
        const long long cnt = (n4 - off < S) ? (n4 - off) : S;
        det_zero<<<512, 256>>>((float4*)det + off, cnt);
    }

    // 3) pass2 (merge + scatter) — must follow the zero-fill
    haar_pass2<<<DIM_B * DIM_F / 8, 256>>>(det);
}

// round 7
// speedup vs baseline: 2.1568x; 2.1568x over previous
#include <cuda_runtime.h>
#include <cstdint>

// HaarWaveletTopK on GB300 (sm_103a) — threshold-candidate design.
// Pass1: pure streaming Haar transform (main + zero detail), rare candidate
//        pushes for |e-o| > THRESH via global atomics. No top-k in hot loop.
// Pass2: warp-per-column top-8 select over candidates + sparse scatter.
//        Exact fallback rescan if a column's candidate set is unusable.
// x: (B=8, T=8192, F=512) fp32.  out = [main | detail], each (B,T,F).

#define DIM_B 8
#define DIM_T 8192
#define DIM_T2 4096
#define DIM_F 512
#define DIM_F2 (DIM_F / 2)              // 256 float2 per row

#define TOPK 8
#define NC 16                            // t-chunks (grid z)
#define T_PER_CHUNK (DIM_T2 / NC)        // 256
#define TSEG 8                           // warps per block
#define NTHREADS (32 * TSEG)             // 256
#define T_PER_THREAD (T_PER_CHUNK / TSEG)    // 32
#define UNROLL 8

#define CAP 96                           // max candidates kept per column
// |e-o| ~ N(0,2). THRESH = 3.6 => p ~= 0.0109/value, mean ~= 45 cands/col.
// P(count < 8) ~ 1e-14, P(count > 96) ~ 1e-14 per column.
#define THRESH 3.6f

typedef unsigned long long u64;
typedef unsigned int u32;

__device__ u32 g_count[DIM_B * DIM_F] = {};          // zero-init at load
__device__ u64 g_cand[DIM_B * DIM_F * CAP];          // masked by count

__device__ __forceinline__ u64 pack_cand(float a, int t, float h)
{
    const u32 pay = ((u32)t << 1) | (h < 0.0f ? 1u : 0u);
    return ((u64)__float_as_uint(a) << 32) | pay;    // a >= 0 -> monotone
}

__device__ __forceinline__ void push_cand(int col, float a, int t, float h)
{
    const u32 slot = atomicAdd(&g_count[col], 1u);
    if (slot < CAP)
        g_cand[(size_t)col * CAP + slot] = pack_cand(a, t, h);
}

// ---------------------------------------------------------------------------
// Pass 1: streaming transform. Loads front-batched (UNROLL pairs) for MLP.
// ---------------------------------------------------------------------------
__global__ __launch_bounds__(NTHREADS)
void haar_pass1(const float2* __restrict__ x2,
                float2* __restrict__ m2,
                float2* __restrict__ d2)
{
    const int lane = threadIdx.x & 31;
    const int ts   = threadIdx.x >> 5;
    const int fc   = blockIdx.x * 32 + lane;     // float2 column (0..255)
    const int b    = blockIdx.y;
    const int c    = blockIdx.z;

    const float2* __restrict__ xb = x2 + (size_t)b * DIM_T * DIM_F2;
    float2* __restrict__ mb       = m2 + (size_t)b * DIM_T * DIM_F2;
    float2* __restrict__ db       = d2 + (size_t)b * DIM_T * DIM_F2;

    const int t0 = c * T_PER_CHUNK + ts * T_PER_THREAD;
    const float2 z2 = make_float2(0.0f, 0.0f);
    const int col0 = b * DIM_F + 2 * fc;

    for (int ib = 0; ib < T_PER_THREAD; ib += UNROLL) {
        float2 e[UNROLL], o[UNROLL];

        // Front-batched loads: 2*UNROLL independent LDG.64 in flight.
#pragma unroll
        for (int i = 0; i < UNROLL; ++i) {
            const size_t re = (size_t)(2 * (t0 + ib + i)) * DIM_F2 + fc;
            e[i] = xb[re];
            o[i] = xb[re + DIM_F2];
        }

#pragma unroll
        for (int i = 0; i < UNROLL; ++i) {
            const int t = t0 + ib + i;
            const size_t re = (size_t)(2 * t) * DIM_F2 + fc;

            float2 low;
            low.x = (e[i].x + o[i].x) * 0.5f;
            low.y = (e[i].y + o[i].y) * 0.5f;

            mb[re]          = low;
            mb[re + DIM_F2] = low;
            db[re]          = z2;
            db[re + DIM_F2] = z2;

            const float hx = e[i].x - o[i].x;
            const float hy = e[i].y - o[i].y;
            const float ax = fabsf(hx);
            const float ay = fabsf(hy);

            if (fmaxf(ax, ay) > THRESH) {        // rare path
                if (ax > THRESH) push_cand(col0,     ax, t, hx);
                if (ay > THRESH) push_cand(col0 + 1, ay, t, hy);
            }
        }
    }
}

// ---------------------------------------------------------------------------
// Pass 2: one warp per (b,f) column.
// ---------------------------------------------------------------------------
__global__ __launch_bounds__(256)
void haar_pass2(const float* __restrict__ x,
                float* __restrict__ out_det)
{
    const int wid_in_blk = threadIdx.x >> 5;
    const int lane       = threadIdx.x & 31;
    const int col        = blockIdx.x * 8 + wid_in_blk;   // 0..4095
    const int b          = col >> 9;
    const int f          = col & (DIM_F - 1);

    const u32 count = g_count[col];

    u64 v0 = 0, v1 = 0, v2 = 0;

    if (count >= TOPK && count <= CAP) {
        // Normal path: masked loads of up to 96 candidates (3 per lane).
        const size_t base = (size_t)col * CAP;
        if (lane           < (int)count) v0 = g_cand[base + lane];
        if (lane + 32      < (int)count) v1 = g_cand[base + lane + 32];
        if (lane + 64      < (int)count) v2 = g_cand[base + lane + 64];
    } else {
        // Fallback (statistically never): exact rescan of the column.
        const float* __restrict__ xb = x + (size_t)b * DIM_T * DIM_F + f;
        u64 L[TOPK];
#pragma unroll
        for (int j = 0; j < TOPK; ++j) L[j] = 0;

        for (int t = lane; t < DIM_T2; t += 32) {
            const float e = xb[(size_t)(2 * t) * DIM_F];
            const float o = xb[(size_t)(2 * t) * DIM_F + DIM_F];
            const float h = e - o;
            const u64 pk  = pack_cand(fabsf(h), t, h);
            if (pk > L[TOPK - 1]) {
                L[TOPK - 1] = pk;
#pragma unroll
                for (int j = TOPK - 1; j > 0; --j)
                    if (L[j] > L[j - 1]) { u64 tt = L[j]; L[j] = L[j - 1]; L[j - 1] = tt; }
            }
        }
        // Feed the same selection machinery: 3 regs can't hold 8; run
        // selection directly over L via per-round warp-max on L[0] stream.
        v0 = L[0]; v1 = L[1]; v2 = L[2];
        // Remaining 5 entries: fold into a second pass by re-inserting the
        // largest of L[3..7] each time one of ours is consumed is complex;
        // instead do full 8-round max over a rotating head below using L[].
        // Simplest correct approach: each lane exposes its 8 sorted entries
        // one at a time.
        u64 res = 0;
        int  hp  = 0;   // per-lane head position into L
#pragma unroll
        for (int r = 0; r < TOPK; ++r) {
            u64 head = (hp < TOPK) ? L[hp] : 0;
            u64 hmax = head;
#pragma unroll
            for (int off = 16; off > 0; off >>= 1) {
                const u64 other = __shfl_xor_sync(0xFFFFFFFFu, hmax, off);
                if (other > hmax) hmax = other;
            }
            const bool mine = (head == hmax) && (hmax != 0);
            const unsigned m = __ballot_sync(0xFFFFFFFFu, mine);
            const int winner = __ffs(m) - 1;
            if (lane == winner) ++hp;
            if (lane == r) res = hmax;
        }
        // Scatter + counter reset, then exit this warp.
        if (lane < TOPK && res != 0) {
            const u32 payv = (u32)res;
            float val = __uint_as_float((u32)(res >> 32)) * 0.5f;
            if (payv & 1) val = -val;
            const int tt = (int)(payv >> 1);
            float* __restrict__ db = out_det + (size_t)b * DIM_T * DIM_F;
            const size_t r0 = (size_t)(2 * tt) * DIM_F + f;
            db[r0]         = val;
            db[r0 + DIM_F] = -val;
        }
        if (lane == 0) g_count[col] = 0;
        return;
    }

    // Sort 3 descending per lane
    u64 t;
    if (v0 < v1) { t = v0; v0 = v1; v1 = t; }
    if (v1 < v2) { t = v1; v1 = v2; v2 = t; }
    if (v0 < v1) { t = v0; v0 = v1; v1 = t; }

    u64 res = 0;   // lane r holds round-r winner
#pragma unroll
    for (int r = 0; r < TOPK; ++r) {
        u64 head = v0;
#pragma unroll
        for (int off = 16; off > 0; off >>= 1) {
            const u64 other = __shfl_xor_sync(0xFFFFFFFFu, head, off);
            if (other > head) head = other;
        }
        const bool mine = (v0 == head) && (head != 0);
        const unsigned m = __ballot_sync(0xFFFFFFFFu, mine);
        const int winner = __ffs(m) - 1;
        if (lane == winner) { v0 = v1; v1 = v2; v2 = 0; }
        if (lane == r) res = head;
    }

    if (lane < TOPK) {
        const u32 payv = (u32)res;
        float val = __uint_as_float((u32)(res >> 32)) * 0.5f;   // |h|*0.5
        if (payv & 1) val = -val;
        const int tt = (int)(payv >> 1);
        float* __restrict__ db = out_det + (size_t)b * DIM_T * DIM_F;
        const size_t r0 = (size_t)(2 * tt) * DIM_F + f;
        db[r0]         = val;
        db[r0 + DIM_F] = -val;
    }

    if (lane == 0) g_count[col] = 0;     // restore invariant for next call
}

extern "C" void kernel_launch(void* const* d_in, const int* in_sizes, int n_in,
                              void* d_out, int out_size)
{
    const float* x = (const float*)d_in[0];
    float* out = (float*)d_out;
    const size_t N = (size_t)out_size / 2;    // elements in `main`
    float* det = out + N;

    dim3 grid1(DIM_F2 / 32, DIM_B, NC);       // 8 x 8 x 16 = 1024 blocks
    haar_pass1<<<grid1, NTHREADS>>>((const float2*)x,
                                    (float2*)out,
                                    (float2*)det);

    haar_pass2<<<DIM_B * DIM_F / 8, 256>>>(x, det);   // 512 blocks
}